// round 17
// baseline (speedup 1.0000x reference)
#include <cuda_runtime.h>
#include <cuda_fp16.h>
#include <math.h>
#include <stdint.h>

// Problem constants
#define T_TOK 4096   // B*S tokens
#define D_DIM 1024   // embed dim
#define U_DIM 4096   // ffn dim
#define E_NUM 8      // experts

// ---------------- scratch (static device globals; no allocation) -----------
__device__ __half g_xh [(size_t)T_TOK * D_DIM];
__device__ __half g_wuh[(size_t)E_NUM * U_DIM * D_DIM];
__device__ __half g_wdh[(size_t)E_NUM * D_DIM * U_DIM];
__device__ __half g_Hh [(size_t)T_TOK * 2 * U_DIM];
__device__ int   g_tok[E_NUM * T_TOK];
__device__ float g_wt [E_NUM * T_TOK];
__device__ int   g_cnt[E_NUM];
__device__ int   g_off[E_NUM];

// ---------------- PTX helpers (baseline sm_80+ ISA only) -------------------
__device__ __forceinline__ uint32_t smem_u32(const void* p) {
    uint32_t a;
    asm("{ .reg .u64 t; cvta.to.shared.u64 t, %1; cvt.u32.u64 %0, t; }" : "=r"(a) : "l"(p));
    return a;
}

#define CP16(dst, src)  asm volatile("cp.async.cg.shared.global [%0], [%1], 16;" :: "r"(dst), "l"(src))
#define CP_COMMIT()     asm volatile("cp.async.commit_group;" ::: "memory")
#define CP_WAIT1()      asm volatile("cp.async.wait_group 1;" ::: "memory")
#define CP_WAIT0()      asm volatile("cp.async.wait_group 0;" ::: "memory")

#define LDSM4(r0, r1, r2, r3, addr) \
    asm volatile("ldmatrix.sync.aligned.m8n8.x4.shared.b16 {%0,%1,%2,%3}, [%4];" \
                 : "=r"(r0), "=r"(r1), "=r"(r2), "=r"(r3) : "r"(addr))

__device__ __forceinline__ void mma16816(float* d, const uint32_t* a, const uint32_t* b) {
    asm volatile(
        "mma.sync.aligned.m16n8k16.row.col.f32.f16.f16.f32 "
        "{%0,%1,%2,%3}, {%4,%5,%6,%7}, {%8,%9}, {%0,%1,%2,%3};"
        : "+f"(d[0]), "+f"(d[1]), "+f"(d[2]), "+f"(d[3])
        : "r"(a[0]), "r"(a[1]), "r"(a[2]), "r"(a[3]), "r"(b[0]), "r"(b[1]));
}

// SMEM tile: 128 rows x 8 chunks of 16B (BK=64 fp16, 128B rows).
// XOR swizzle: chunk' = chunk ^ (row & 7).
__device__ __forceinline__ uint32_t tile_off(int row, int chunk) {
    return (uint32_t)(row * 128 + ((chunk ^ (row & 7)) << 4));
}

__device__ __forceinline__ float gelu_exact(float v) {
    return 0.5f * v * (1.f + erff(v * 0.70710678118654752f));
}

// ---------------- preprocessing: fp32 -> fp16 (x, w_up, w_down in one) -----
#define N_X ((int)(T_TOK * D_DIM))                 // 4,194,304
#define N_W ((int)(E_NUM * U_DIM * D_DIM))         // 33,554,432

__global__ void prep_kernel(const float* __restrict__ x,
                            const float* __restrict__ wu,
                            const float* __restrict__ wd,
                            __half* __restrict__ xh,
                            __half* __restrict__ wuh,
                            __half* __restrict__ wdh) {
    int gi = (blockIdx.x * blockDim.x + threadIdx.x) * 8;
    const float* src; __half* dst; int i;
    if (gi < N_X)            { src = x;  dst = xh;  i = gi; }
    else if (gi < N_X + N_W) { src = wu; dst = wuh; i = gi - N_X; }
    else                     { src = wd; dst = wdh; i = gi - N_X - N_W; }
    float4 a = *(const float4*)(src + i);
    float4 b = *(const float4*)(src + i + 4);
    __half2 h[4];
    h[0] = __floats2half2_rn(a.x, a.y); h[1] = __floats2half2_rn(a.z, a.w);
    h[2] = __floats2half2_rn(b.x, b.y); h[3] = __floats2half2_rn(b.z, b.w);
    *(uint4*)(dst + i) = *(uint4*)h;
}

// ---------------- router ----------------------------------------------------
__global__ void zero_cnt_kernel() {
    if (threadIdx.x < E_NUM) g_cnt[threadIdx.x] = 0;
}

__global__ void router_kernel(const float* __restrict__ x,
                              const float* __restrict__ wr) {
    int t    = blockIdx.x * 4 + (threadIdx.x >> 5);
    int lane = threadIdx.x & 31;
    if (t >= T_TOK) return;
    const float* xr = x + (size_t)t * D_DIM;

    float logit[E_NUM];
#pragma unroll
    for (int e = 0; e < E_NUM; e++) {
        const float* w = wr + e * D_DIM;
        float s = 0.f;
        for (int i = lane; i < D_DIM; i += 32)
            s += xr[i] * w[i];
#pragma unroll
        for (int o = 16; o > 0; o >>= 1)
            s += __shfl_xor_sync(0xffffffffu, s, o);
        logit[e] = s;
    }

    if (lane == 0) {
        int e0 = 0; float l0 = logit[0];
#pragma unroll
        for (int e = 1; e < E_NUM; e++)
            if (logit[e] > l0) { l0 = logit[e]; e0 = e; }
        int e1 = -1; float l1 = -INFINITY;
#pragma unroll
        for (int e = 0; e < E_NUM; e++)
            if (e != e0 && logit[e] > l1) { l1 = logit[e]; e1 = e; }

        float p1 = expf(l1 - l0);
        float inv = 1.f / (1.f + p1);
        float w0 = inv, w1 = p1 * inv;

        int p;
        p = atomicAdd(&g_cnt[e0], 1);
        g_tok[e0 * T_TOK + p] = t;  g_wt[e0 * T_TOK + p] = w0;
        p = atomicAdd(&g_cnt[e1], 1);
        g_tok[e1 * T_TOK + p] = t;  g_wt[e1 * T_TOK + p] = w1;
    }
}

__global__ void offsets_kernel() {
    if (threadIdx.x == 0) {
        int acc = 0;
#pragma unroll
        for (int e = 0; e < E_NUM; e++) { g_off[e] = acc; acc += g_cnt[e]; }
    }
}

// ---------------- grouped GEMM: fp16 mma, single pass ----------------------
// C[m,n] = sum_k A[m,k]*B[n,k], fp32 accumulators; A gathered.
// Tile BM=128, BN=128, BK=64; 8 warps each 32(M) x 64(N).
// 3-stage cp.async pipeline + register double-buffered ldmatrix frags.
// KSPLIT: split-K via blockIdx.z = e*KSPLIT + kz; atomicAdd accumulates,
// bias added only by the kz==0 slice (down GEMM).

static constexpr int SMEM_TILES  = 1024;
static constexpr int STAGE_BYTES = 32768;
static constexpr int SMEM_BYTES  = SMEM_TILES + 3 * STAGE_BYTES;  // 99328

template<int KDIM, bool IS_UP, int KSPLIT>
__global__ void __launch_bounds__(256, 2)
moe_mma(const __half* __restrict__ Ah, const __half* __restrict__ Wh,
        const float* __restrict__ bias, float* __restrict__ out)
{
    constexpr int NTOT = IS_UP ? U_DIM : D_DIM;
    constexpr int NT   = KDIM / 64 / KSPLIT;   // k-tiles for this slice

    int e   = blockIdx.z / KSPLIT;
    int kz  = blockIdx.z % KSPLIT;
    int n_e = g_cnt[e];
    int m0  = blockIdx.y * 128;
    if (m0 >= n_e) return;
    int n0  = blockIdx.x * 128;
    int off = g_off[e];

    int tid  = threadIdx.x;
    int lane = tid & 31;
    int wid  = tid >> 5;
    int wm   = (wid & 3) * 32;   // warp M offset
    int wn   = (wid >> 2) * 64;  // warp N offset

    extern __shared__ __align__(16) char smem[];
    uint32_t sb = smem_u32(smem);
    int*   s_tok = (int*)(smem);
    float* s_wt  = (float*)(smem + 512);

    if (tid < 128) {
        int grow = m0 + tid;
        int idx  = e * T_TOK + (grow < n_e ? grow : n_e - 1);
        s_tok[tid] = g_tok[idx];
        s_wt[tid]  = g_wt[idx];
    }
    __syncthreads();

    // ---- per-thread cp.async slots: chunk c, rows r0+32j (j=0..3)
    int c  = tid & 7;              // 16B chunk within 128B row
    int r0 = tid >> 3;             // 0..31
    int kbase = kz * NT * 64;
    uint32_t d_off[4];
    const __half *a_src[4], *b_src[4];
    const __half* We = Wh + (size_t)e * NTOT * KDIM;
#pragma unroll
    for (int j = 0; j < 4; j++) {
        int row = r0 + 32 * j;
        d_off[j] = tile_off(row, c);
        if (IS_UP) {
            a_src[j] = Ah + (size_t)s_tok[row] * KDIM + kbase + c * 8;
        } else {
            int gr = m0 + row; if (gr >= n_e) gr = n_e - 1;
            a_src[j] = Ah + (size_t)(off + gr) * KDIM + kbase + c * 8;
        }
        b_src[j] = We + (size_t)(n0 + row) * KDIM + kbase + c * 8;
    }

    auto load_stage = [&](int kt, int s) {
        uint32_t tb = sb + SMEM_TILES + s * STAGE_BYTES;
        int ko = kt * 64;
#pragma unroll
        for (int j = 0; j < 4; j++) {
            CP16(tb +         d_off[j], a_src[j] + ko);
            CP16(tb + 16384 + d_off[j], b_src[j] + ko);
        }
        CP_COMMIT();
    };

    // ---- ldmatrix address components (fixed per thread)
    int arow = wm + (lane & 15);
    int achk = lane >> 4;                              // + ks*2
    int brow = wn + ((lane >> 4) << 3) + (lane & 7);
    int bchk = (lane >> 3) & 1;                        // + ks*2

    float acc[2][8][4] = {};
    uint32_t aF[2][2][4];   // [buf][mi][frag]
    uint32_t bF[2][4][4];   // [buf][np][frag]

    auto load_frags = [&](uint32_t tb, int ks, int buf) {
#pragma unroll
        for (int mi = 0; mi < 2; mi++) {
            uint32_t ao = tile_off(arow + mi * 16, ks * 2 + achk);
            LDSM4(aF[buf][mi][0], aF[buf][mi][1], aF[buf][mi][2], aF[buf][mi][3], tb + ao);
        }
#pragma unroll
        for (int np = 0; np < 4; np++) {
            uint32_t bo = tile_off(brow + np * 16, ks * 2 + bchk);
            LDSM4(bF[buf][np][0], bF[buf][np][1], bF[buf][np][2], bF[buf][np][3],
                  tb + 16384 + bo);
        }
    };

    load_stage(0, 0);
    if (NT > 1) load_stage(1, 1);
    for (int kt = 0; kt < NT; kt++) {
        if (kt + 1 < NT) CP_WAIT1();
        else             CP_WAIT0();
        __syncthreads();

        if (kt + 2 < NT) load_stage(kt + 2, (kt + 2) % 3);

        uint32_t tb = sb + SMEM_TILES + (kt % 3) * STAGE_BYTES;
        load_frags(tb, 0, 0);
#pragma unroll
        for (int ks = 0; ks < 4; ks++) {       // 4 x K=16 sub-tiles
            int cur = ks & 1;
            if (ks < 3) load_frags(tb, ks + 1, cur ^ 1);   // prefetch next frags
#pragma unroll
            for (int np = 0; np < 4; np++) {
#pragma unroll
                for (int mi = 0; mi < 2; mi++) {
#pragma unroll
                    for (int sub = 0; sub < 2; sub++)
                        mma16816(acc[mi][np * 2 + sub], aF[cur][mi],
                                 &bF[cur][np][sub * 2]);
                }
            }
        }
    }

    // ---- epilogue. acc[mi][nf]: {c0,c1}=row r cols 2q,2q+1; {c2,c3}=row r+8
    int r = lane >> 2, q = lane & 3;
    const float* brow_bias = bias + (size_t)e * NTOT;
    bool add_bias = (kz == 0);
#pragma unroll
    for (int mi = 0; mi < 2; mi++) {
#pragma unroll
        for (int nf = 0; nf < 8; nf++) {
            float* a4 = acc[mi][nf];
            int col  = n0 + wn + nf * 8 + 2 * q;
            float bz0 = add_bias ? brow_bias[col]     : 0.f;
            float bz1 = add_bias ? brow_bias[col + 1] : 0.f;
#pragma unroll
            for (int h = 0; h < 2; h++) {
                int local = wm + mi * 16 + r + h * 8;
                if (m0 + local >= n_e) continue;
                float v0 = a4[h * 2 + 0] + bz0;
                float v1 = a4[h * 2 + 1] + bz1;
                if (IS_UP) {
                    v0 = gelu_exact(v0); v1 = gelu_exact(v1);
                    size_t o = (size_t)(off + m0 + local) * U_DIM + col;
                    *(__half2*)(g_Hh + o) = __floats2half2_rn(v0, v1);
                } else {
                    int   tok = s_tok[local];
                    float wgt = s_wt[local];
                    float* op = out + (size_t)tok * D_DIM + col;
                    atomicAdd(op,     wgt * v0);
                    atomicAdd(op + 1, wgt * v1);
                }
            }
        }
    }
}

// ---------------- launch -----------------------------------------------------
extern "C" void kernel_launch(void* const* d_in, const int* in_sizes, int n_in,
                              void* d_out, int out_size) {
    const float* x  = (const float*)d_in[0];
    const float* wr = (const float*)d_in[1];
    const float* wu = (const float*)d_in[2];
    const float* bu = (const float*)d_in[3];
    const float* wd = (const float*)d_in[4];
    const float* bd = (const float*)d_in[5];
    float* out = (float*)d_out;

    cudaFuncSetAttribute(moe_mma<D_DIM, true, 1>,
                         cudaFuncAttributeMaxDynamicSharedMemorySize, SMEM_BYTES);
    cudaFuncSetAttribute(moe_mma<U_DIM, false, 2>,
                         cudaFuncAttributeMaxDynamicSharedMemorySize, SMEM_BYTES);

    __half *xh, *wuh, *wdh, *Hh;
    cudaGetSymbolAddress((void**)&xh,  g_xh);
    cudaGetSymbolAddress((void**)&wuh, g_wuh);
    cudaGetSymbolAddress((void**)&wdh, g_wdh);
    cudaGetSymbolAddress((void**)&Hh,  g_Hh);

    cudaMemsetAsync(out, 0, (size_t)out_size * sizeof(float), 0);
    zero_cnt_kernel<<<1, 32>>>();
    router_kernel<<<T_TOK / 4, 128>>>(x, wr);
    offsets_kernel<<<1, 32>>>();

    int total = N_X + 2 * N_W;                     // 71,303,168 (8 | total)
    prep_kernel<<<total / (256 * 8), 256>>>(x, wu, wd, xh, wuh, wdh);

    // up: M=8192 routed rows, N=4096, K=1024
    moe_mma<D_DIM, true, 1><<<dim3(U_DIM / 128, T_TOK / 128, E_NUM), 256, SMEM_BYTES>>>(
        xh, wuh, bu, nullptr);

    // down: M=8192 routed rows, N=1024, K=4096, split-K=2 (1024 CTAs)
    moe_mma<U_DIM, false, 2><<<dim3(D_DIM / 128, T_TOK / 128, E_NUM * 2), 256, SMEM_BYTES>>>(
        Hh, wdh, bd, out);
}